// round 3
// baseline (speedup 1.0000x reference)
#include <cuda_runtime.h>
#include <cstdint>

// ---------------- problem constants ----------------
#define NB 64
#define HP 58
#define PIX (HP * HP)                  // 3364 padded pixels per image
#define ROWS_TOTAL (NB * PIX)          // 215296
#define GUARD 64
#define AROWS (ROWS_TOTAL + 2 * GUARD) // 215424
#define NTILES (ROWS_TOTAL / 128)      // 1682 exact

// ---------------- GEMM smem layout (dynamic) ----------------
#define SM_B 0
#define B_BYTES 147456                 // 9 taps * 4 ksteps * 16 groups * 256 B
#define SM_A 147456
#define STAGE 16384                    // 128 rows x 128 B int8
#define DSMEM (SM_A + 3 * STAGE)       // 196608

// ---------------- device scratch (no allocation allowed) ----------------
__device__ int8_t   g_A8[(size_t)AROWS * 128];   // padded NHWC int8 signs
__device__ uint32_t g_Wfrag[9 * 4 * 16 * 64];    // B in IMMA fragment-linear order
__device__ float    g_sA[128];                    // scale_o * gamma_o * rsqrt(var+eps)
__device__ float    g_sB[128];                    // beta_o - mean_o * inv_o

// ---------------- helpers ----------------
__device__ __forceinline__ uint32_t smem_u32(const void* p) {
    uint32_t a;
    asm("{ .reg .u64 t; cvta.to.shared.u64 t, %1; cvt.u32.u64 %0, t; }" : "=r"(a) : "l"(p));
    return a;
}
#define CP_ASYNC16(dst, src) \
    asm volatile("cp.async.cg.shared.global [%0], [%1], 16;" :: "r"(dst), "l"(src) : "memory")
#define CP_COMMIT asm volatile("cp.async.commit_group;" ::: "memory")
#define CP_WAITG2 asm volatile("cp.async.wait_group 2;" ::: "memory")

__device__ __forceinline__ void lds32(uint32_t& v, uint32_t a) {
    asm volatile("ld.shared.b32 %0, [%1];" : "=r"(v) : "r"(a));
}
__device__ __forceinline__ void lds64(uint32_t& v0, uint32_t& v1, uint32_t a) {
    asm volatile("ld.shared.v2.b32 {%0,%1}, [%2];" : "=r"(v0), "=r"(v1) : "r"(a));
}
__device__ __forceinline__ void mma_s8(int& c0, int& c1, int& c2, int& c3,
                                       uint32_t a0, uint32_t a1, uint32_t a2, uint32_t a3,
                                       uint32_t b0, uint32_t b1) {
    asm volatile(
        "mma.sync.aligned.m16n8k32.row.col.s32.s8.s8.s32 "
        "{%0,%1,%2,%3}, {%4,%5,%6,%7}, {%8,%9}, {%0,%1,%2,%3};"
        : "+r"(c0), "+r"(c1), "+r"(c2), "+r"(c3)
        : "r"(a0), "r"(a1), "r"(a2), "r"(a3), "r"(b0), "r"(b1));
}

// ---------------- K0a: fold scales ----------------
__global__ void k_scales(const float* __restrict__ w, const float* __restrict__ gamma,
                         const float* __restrict__ beta, const float* __restrict__ mean,
                         const float* __restrict__ var) {
    int o = blockIdx.x;
    int t = threadIdx.x;
    __shared__ float red[128];
    const float* wp = w + (o * 128 + t) * 9;
    float acc = 0.f;
#pragma unroll
    for (int k = 0; k < 9; k++) acc += fabsf(wp[k]);
    red[t] = acc;
    __syncthreads();
#pragma unroll
    for (int s = 64; s > 0; s >>= 1) {
        if (t < s) red[t] += red[t + s];
        __syncthreads();
    }
    if (t == 0) {
        float scale = red[0] * (1.0f / 1152.0f);
        float inv = gamma[o] * rsqrtf(var[o] + 1e-5f);
        g_sA[o] = scale * inv;
        g_sB[o] = beta[o] - mean[o] * inv;
    }
}

// ---------------- K0b: sign(w) in IMMA B-fragment-linear order ----------------
// block (tap,kstep,g): lane t holds b0 = signs of c = kb..kb+3, b1 = kb+16..kb+19
// for out-channel o = g*8 + t/4, kb = kstep*32 + (t%4)*4.
__global__ void k_wfrag(const float* __restrict__ w) {
    int idx = blockIdx.x * 128 + threadIdx.x;  // 18432 total
    if (idx >= 9 * 4 * 16 * 32) return;
    int lane = idx & 31;
    int g = (idx >> 5) & 15;
    int ks = (idx >> 9) & 3;
    int tap = idx >> 11;
    int o = g * 8 + (lane >> 2);
    int cb = ks * 32 + (lane & 3) * 4;
    uint32_t b0 = 0, b1 = 0;
#pragma unroll
    for (int j = 0; j < 4; j++) {
        float v0 = w[(o * 128 + cb + j) * 9 + tap];
        float v1 = w[(o * 128 + cb + 16 + j) * 9 + tap];
        uint32_t s0 = (v0 > 0.f) ? 0x01u : (v0 < 0.f ? 0xFFu : 0u);
        uint32_t s1 = (v1 > 0.f) ? 0x01u : (v1 < 0.f ? 0xFFu : 0u);
        b0 |= s0 << (8 * j);
        b1 |= s1 << (8 * j);
    }
    int bi = (tap * 4 + ks) * 16 + g;
    g_Wfrag[bi * 64 + lane * 2] = b0;
    g_Wfrag[bi * 64 + lane * 2 + 1] = b1;
}

// ---------------- K1: x (NCHW f32) -> padded NHWC int8 signs ----------------
__global__ void k_act(const float* __restrict__ x) {
    int hp = blockIdx.x;   // padded row 0..57
    int n = blockIdx.y;    // image
    int tid = threadIdx.x; // 256
    uint32_t* ga = (uint32_t*)g_A8;
    size_t base = ((size_t)GUARD + (size_t)n * PIX + (size_t)hp * HP) * 32; // words
    if (hp == 0 || hp == HP - 1) {
        for (int i = tid; i < HP * 32; i += 256) ga[base + i] = 0u;
        return;
    }
    __shared__ float s[128 * 57];
    const float* xp = x + (size_t)n * 128 * 3136 + (hp - 1) * 56;
    for (int i = tid; i < 128 * 56; i += 256) {
        int c = i / 56;
        int wq = i - c * 56;
        s[c * 57 + wq] = xp[(size_t)c * 3136 + wq];
    }
    __syncthreads();
    for (int i = tid; i < HP * 32; i += 256) {
        int wq = i >> 5;       // padded col
        int j = i & 31;        // channel quad
        uint32_t word = 0;
        if (wq >= 1 && wq <= 56) {
#pragma unroll
            for (int b2 = 0; b2 < 4; b2++) {
                float f = s[(4 * j + b2) * 57 + (wq - 1)];
                uint32_t sg = (f > 0.f) ? 0x01u : (f < 0.f ? 0xFFu : 0u);
                word |= sg << (8 * b2);
            }
        }
        ga[base + i] = word;
    }
}

// ---------------- GEMM: persistent IMMA kernel ----------------
__global__ void __launch_bounds__(256, 1)
k_gemm(const float* __restrict__ x, float* __restrict__ out) {
    extern __shared__ char sm[];
    const uint32_t smb = smem_u32(sm);
    const int tid = threadIdx.x;
    const int lane = tid & 31;
    const int wid = tid >> 5;
    const int wm = wid & 3;    // 4 warps along M (32 rows each)
    const int wn = wid >> 2;   // 2 warps along N (64 cols each)

    // resident B copy (group #0)
    {
        const char* src = (const char*)g_Wfrag;
        for (int j = 0; j < 36; j++) {
            int ch = tid + j * 256;
            CP_ASYNC16(smb + SM_B + ch * 16, src + ch * 16);
        }
        CP_COMMIT;
    }

    auto issueA = [&](int tap, int m) {
        int off = (tap / 3) * 58 + (tap % 3) - 59;
        const int8_t* src = g_A8 + ((size_t)(GUARD + m * 128 + off)) * 128;
        uint32_t dst0 = smb + SM_A + (tap % 3) * STAGE;
#pragma unroll
        for (int j = 0; j < 4; j++) {
            int ch = tid + j * 256;
            int row = ch >> 3;
            int c16 = ch & 7;
            uint32_t d = dst0 + row * 128 + ((c16 * 16) ^ ((row & 7) << 4));
            CP_ASYNC16(d, src + ch * 16);
        }
        CP_COMMIT;
    };

    const int stride = gridDim.x;
    const int m0 = blockIdx.x;
    if (m0 < NTILES) { issueA(0, m0); issueA(1, m0); }
    else { CP_COMMIT; CP_COMMIT; }

    for (int m = m0; m < NTILES; m += stride) {
        int acc[2][8][4];
#pragma unroll
        for (int a = 0; a < 2; a++)
#pragma unroll
            for (int f = 0; f < 8; f++)
#pragma unroll
                for (int e = 0; e < 4; e++) acc[a][f][e] = 0;

#pragma unroll 1
        for (int tap = 0; tap < 9; tap++) {
            __syncthreads();                 // all warps done with stage (tap+2)%3's old data
            int mn = m + stride;
            if (tap < 7) issueA(tap + 2, m);
            else if (mn < NTILES) issueA(tap - 7, mn);
            else CP_COMMIT;
            CP_WAITG2;                       // current tap's stage complete (this thread)
            __syncthreads();                 // visibility of all threads' cp.async

            uint32_t aBase = smb + SM_A + (tap % 3) * STAGE + (wm * 32 + (lane >> 2)) * 128;
            uint32_t bBase = smb + SM_B + ((tap * 4) * 16 + wn * 8) * 256 + lane * 8;
#pragma unroll
            for (int ks = 0; ks < 4; ks++) {
                uint32_t colA = (uint32_t)((ks * 32 + (lane & 3) * 4) ^ ((lane >> 2) << 4));
                uint32_t am0 = aBase + colA;
                uint32_t a0, a1, a2, a3, a4, a5, a6, a7;
                lds32(a0, am0);
                lds32(a1, am0 + 1024);
                lds32(a2, am0 ^ 16);
                lds32(a3, (am0 + 1024) ^ 16);
                lds32(a4, am0 + 2048);
                lds32(a5, am0 + 3072);
                lds32(a6, (am0 + 2048) ^ 16);
                lds32(a7, (am0 + 3072) ^ 16);
#pragma unroll
                for (int f = 0; f < 8; f++) {
                    uint32_t b0, b1;
                    lds64(b0, b1, bBase + (ks * 16 + f) * 256);
                    mma_s8(acc[0][f][0], acc[0][f][1], acc[0][f][2], acc[0][f][3],
                           a0, a1, a2, a3, b0, b1);
                    mma_s8(acc[1][f][0], acc[1][f][1], acc[1][f][2], acc[1][f][3],
                           a4, a5, a6, a7, b0, b1);
                }
            }
        }

        // ---- epilogue: BN affine + residual, coalesced 32B-sector stores ----
        int ofs[4];
        bool val[4];
        int r0 = m * 128 + wm * 32 + (lane >> 2);
#pragma unroll
        for (int v = 0; v < 4; v++) {
            int p = r0 + v * 8;
            int n = p / PIX;
            int rem = p - n * PIX;
            int hq = rem / HP;
            int wq = rem - hq * HP;
            val[v] = (hq >= 1) && (hq <= 56) && (wq >= 1) && (wq <= 56);
            ofs[v] = n * 401408 + (hq - 1) * 56 + (wq - 1);
        }
        int cb = wn * 64 + (lane & 3) * 2;
#pragma unroll
        for (int f = 0; f < 8; f++) {
            int c0 = cb + f * 8;
            float s0 = g_sA[c0], t0 = g_sB[c0];
            float s1 = g_sA[c0 + 1], t1 = g_sB[c0 + 1];
            int o0 = c0 * 3136;
            int o1 = o0 + 3136;
#pragma unroll
            for (int v = 0; v < 4; v++) {
                if (!val[v]) continue;
                int mf = v >> 1;
                int e0 = (v & 1) * 2;
                float x0 = x[ofs[v] + o0];
                float x1 = x[ofs[v] + o1];
                out[ofs[v] + o0] = (float)acc[mf][f][e0] * s0 + t0 + x0;
                out[ofs[v] + o1] = (float)acc[mf][f][e0 + 1] * s1 + t1 + x1;
            }
        }
    }
}

// ---------------- launch ----------------
extern "C" void kernel_launch(void* const* d_in, const int* in_sizes, int n_in,
                              void* d_out, int out_size) {
    (void)in_sizes; (void)n_in; (void)out_size;
    const float* x     = (const float*)d_in[0];
    const float* w     = (const float*)d_in[1];
    const float* gamma = (const float*)d_in[2];
    const float* beta  = (const float*)d_in[3];
    const float* mean  = (const float*)d_in[4];
    const float* var   = (const float*)d_in[5];
    float* out = (float*)d_out;

    cudaFuncSetAttribute(k_gemm, cudaFuncAttributeMaxDynamicSharedMemorySize, DSMEM);

    k_scales<<<128, 128>>>(w, gamma, beta, mean, var);
    k_wfrag<<<144, 128>>>(w);
    k_act<<<dim3(58, 64), 256>>>(x);

    int dev = 0;
    cudaGetDevice(&dev);
    int smc = 0;
    if (cudaDeviceGetAttribute(&smc, cudaDevAttrMultiProcessorCount, dev) != cudaSuccess || smc <= 0)
        smc = 148;
    k_gemm<<<smc, 256, DSMEM>>>(x, out);
}

// round 4
// speedup vs baseline: 1.9920x; 1.9920x over previous
#include <cuda_runtime.h>
#include <cstdint>

// ---------------- problem constants ----------------
#define NB 64
#define HP 58
#define PIX (HP * HP)                  // 3364 padded pixels per image
#define ROWS_TOTAL (NB * PIX)          // 215296
#define GUARD 64
#define AROWS (ROWS_TOTAL + 2 * GUARD)

// ---------------- device scratch (no allocation allowed) ----------------
__device__ uint4    g_Abit[AROWS];        // bit-packed sign(x), padded NHWC (bit=1 <=> +1)
__device__ uint32_t g_Wbit[128 * 9 * 4];  // bit-packed sign(w): [o][tap][4 words]
__device__ float    g_sA[128];            // scale_o * gamma_o * rsqrt(var+eps)
__device__ float    g_sB[128];            // beta_o - mean_o * inv_o
__device__ float    g_alpha[128];         // -2 * sA
__device__ int      g_colsum[128 * 9];    // sum_c sign(w)[o,c,tap]
__device__ float    g_bias[16 * 128];     // (1152 + corr[type]) * sA + sB

// ---------------- K0: weights -> bits + colsums + folded scales ----------------
__global__ void k_wbit(const float* __restrict__ w, const float* __restrict__ gamma,
                       const float* __restrict__ beta, const float* __restrict__ mean,
                       const float* __restrict__ var) {
    int o = blockIdx.x;
    int c = threadIdx.x;      // input channel 0..127
    int lane = c & 31;
    int g = c >> 5;           // word index (channel group of 32)
    __shared__ float redf[128];
    __shared__ uint32_t s_w[36];

    const float* wp = w + (o * 128 + c) * 9;
    float wv[9];
    float acc = 0.f;
#pragma unroll
    for (int t = 0; t < 9; t++) { wv[t] = wp[t]; acc += fabsf(wv[t]); }
    redf[c] = acc;

    // sign bits via ballot (bit lane = channel g*32+lane)
#pragma unroll
    for (int t = 0; t < 9; t++) {
        unsigned m = __ballot_sync(0xFFFFFFFFu, wv[t] > 0.f);
        if (lane == 0) s_w[t * 4 + g] = m;
    }
    __syncthreads();
#pragma unroll
    for (int s = 64; s > 0; s >>= 1) {
        if (c < s) redf[c] += redf[c + s];
        __syncthreads();
    }
    if (c < 9) {
        int t = c;
        uint32_t b0 = s_w[t * 4 + 0], b1 = s_w[t * 4 + 1], b2 = s_w[t * 4 + 2], b3 = s_w[t * 4 + 3];
        g_Wbit[(o * 9 + t) * 4 + 0] = b0;
        g_Wbit[(o * 9 + t) * 4 + 1] = b1;
        g_Wbit[(o * 9 + t) * 4 + 2] = b2;
        g_Wbit[(o * 9 + t) * 4 + 3] = b3;
        g_colsum[o * 9 + t] = 2 * (__popc(b0) + __popc(b1) + __popc(b2) + __popc(b3)) - 128;
    }
    if (c == 0) {
        float scale = redf[0] * (1.0f / 1152.0f);
        float inv = gamma[o] * rsqrtf(var[o] + 1e-5f);
        float sA = scale * inv;
        g_sA[o] = sA;
        g_sB[o] = beta[o] - mean[o] * inv;
        g_alpha[o] = -2.0f * sA;
    }
}

// ---------------- K0b: boundary-type bias table ----------------
__global__ void k_tab() {
    int o = threadIdx.x;   // 128
    float sA = g_sA[o];
    float sB = g_sB[o];
    for (int type = 0; type < 16; type++) {
        int corr = 0;
#pragma unroll
        for (int t = 0; t < 9; t++) {
            int dy = t / 3 - 1, dx = t % 3 - 1;
            bool inval = ((type & 1) && dy < 0) || ((type & 2) && dy > 0) ||
                         ((type & 4) && dx < 0) || ((type & 8) && dx > 0);
            if (inval) corr += g_colsum[o * 9 + t];
        }
        g_bias[type * 128 + o] = (float)(1152 + corr) * sA + sB;
    }
}

// ---------------- K1: x (NCHW f32) -> padded bit-packed signs ----------------
__global__ void k_actbit(const float* __restrict__ x) {
    int hp = blockIdx.x;   // padded row 0..57
    int n = blockIdx.y;
    int tid = threadIdx.x; // 256
    uint32_t* ga = (uint32_t*)g_Abit;
    size_t rowbase = ((size_t)GUARD + (size_t)n * PIX + (size_t)hp * HP) * 4;
    if (hp == 0 || hp == HP - 1) {
        for (int i = tid; i < HP * 4; i += 256) ga[rowbase + i] = 0u;
        return;
    }
    __shared__ float s[128 * 57];
    const float* xp = x + (size_t)n * 128 * 3136 + (size_t)(hp - 1) * 56;
    for (int i = tid; i < 128 * 56; i += 256) {
        int c = i / 56;
        int wq = i - c * 56;
        s[c * 57 + wq] = xp[(size_t)c * 3136 + wq];
    }
    __syncthreads();
    int lane = tid & 31;
    int warp = tid >> 5;
    for (int j = warp; j < HP * 4; j += 8) {
        int wp = j >> 2;
        int g = j & 3;
        float v = (wp >= 1 && wp <= 56) ? s[(g * 32 + lane) * 57 + (wp - 1)] : -1.0f;
        unsigned m = __ballot_sync(0xFFFFFFFFu, v > 0.f);
        if (lane == 0) ga[rowbase + j] = m;
    }
}

// ---------------- K2: XNOR-popcount conv + BN + residual ----------------
__global__ void __launch_bounds__(256)
k_pop(const float* __restrict__ x, float* __restrict__ out) {
    __shared__ uint32_t sW[128 * 9 * 4];   // 18 KB
    __shared__ float s_bias[16 * 128];     // 8 KB
    __shared__ float s_alpha[128];

    int tid = threadIdx.x;
    for (int i = tid; i < 128 * 9 * 4; i += 256) sW[i] = g_Wbit[i];
    for (int i = tid; i < 16 * 128; i += 256) s_bias[i] = g_bias[i];
    if (tid < 128) s_alpha[tid] = g_alpha[tid];
    __syncthreads();

    int p = blockIdx.x * 256 + tid;        // 0..200703 (784*256 exact)
    int n = p / 3136;
    int rem = p - n * 3136;
    int h = rem / 56;
    int w = rem - h * 56;

    // load 9 tap words (registers), padded-grid addressing
    int arow = GUARD + n * PIX + (h + 1) * HP + (w + 1);
    uint4 A[9];
#pragma unroll
    for (int t = 0; t < 9; t++) {
        int dy = t / 3 - 1, dx = t % 3 - 1;
        A[t] = g_Abit[arow + dy * HP + dx];
    }
    int type = (h == 0 ? 1 : 0) | (h == 55 ? 2 : 0) | (w == 0 ? 4 : 0) | (w == 55 ? 8 : 0);
    const float* s_biasT = s_bias + type * 128;
    int base = n * 401408 + h * 56 + w;

    const uint4* Wv = (const uint4*)sW;
#pragma unroll 1
    for (int oc = 0; oc < 8; oc++) {
        float xv[16];
#pragma unroll
        for (int j = 0; j < 16; j++) xv[j] = x[base + (oc * 16 + j) * 3136];
#pragma unroll
        for (int j = 0; j < 16; j++) {
            int o = oc * 16 + j;
            int D = 0;
#pragma unroll
            for (int t = 0; t < 9; t++) {
                uint4 wv = Wv[o * 9 + t];
                D += __popc(A[t].x ^ wv.x) + __popc(A[t].y ^ wv.y) +
                     __popc(A[t].z ^ wv.z) + __popc(A[t].w ^ wv.w);
            }
            out[base + o * 3136] = fmaf((float)D, s_alpha[o], s_biasT[o]) + xv[j];
        }
    }
}

// ---------------- launch ----------------
extern "C" void kernel_launch(void* const* d_in, const int* in_sizes, int n_in,
                              void* d_out, int out_size) {
    (void)in_sizes; (void)n_in; (void)out_size;
    const float* x     = (const float*)d_in[0];
    const float* w     = (const float*)d_in[1];
    const float* gamma = (const float*)d_in[2];
    const float* beta  = (const float*)d_in[3];
    const float* mean  = (const float*)d_in[4];
    const float* var   = (const float*)d_in[5];
    float* out = (float*)d_out;

    k_actbit<<<dim3(HP, NB), 256>>>(x);
    k_wbit<<<128, 128>>>(w, gamma, beta, mean, var);
    k_tab<<<1, 128>>>();
    k_pop<<<784, 256>>>(x, out);
}

// round 5
// speedup vs baseline: 2.1120x; 1.0603x over previous
#include <cuda_runtime.h>
#include <cstdint>

// ---------------- problem constants ----------------
#define NB 64
#define HP 58
#define PIX (HP * HP)                  // 3364 padded pixels per image
#define ROWS_TOTAL (NB * PIX)          // 215296
#define GUARD 64
#define AROWS (ROWS_TOTAL + 2 * GUARD)

// ---------------- device scratch (no allocation allowed) ----------------
__device__ uint4    g_Abit[AROWS];        // bit-packed sign(x), padded NHWC (bit=1 <=> +1)
__device__ uint32_t g_Wbit[128 * 9 * 4];  // bit-packed sign(w): [o][tap][4 words]
__device__ float    g_alpha[128];         // -2 * scale_o * gamma_o * rsqrt(var+eps)
__device__ float    g_bias[16 * 128];     // (1152 + corr[type]) * sA + sB

// ---------------- K0: weights -> bits + folded scales + boundary bias table ----------------
__global__ void k_wbit(const float* __restrict__ w, const float* __restrict__ gamma,
                       const float* __restrict__ beta, const float* __restrict__ mean,
                       const float* __restrict__ var) {
    int o = blockIdx.x;
    int c = threadIdx.x;      // input channel 0..127
    int lane = c & 31;
    int g = c >> 5;           // word index (channel group of 32)
    __shared__ float redf[128];
    __shared__ uint32_t s_w[36];
    __shared__ int s_col[9];

    const float* wp = w + (o * 128 + c) * 9;
    float wv[9];
    float acc = 0.f;
#pragma unroll
    for (int t = 0; t < 9; t++) { wv[t] = wp[t]; acc += fabsf(wv[t]); }
    redf[c] = acc;

    // sign bits via ballot (bit lane = channel g*32+lane)
#pragma unroll
    for (int t = 0; t < 9; t++) {
        unsigned m = __ballot_sync(0xFFFFFFFFu, wv[t] > 0.f);
        if (lane == 0) s_w[t * 4 + g] = m;
    }
    __syncthreads();
#pragma unroll
    for (int s = 64; s > 0; s >>= 1) {
        if (c < s) redf[c] += redf[c + s];
        __syncthreads();
    }
    if (c < 9) {
        int t = c;
        uint32_t b0 = s_w[t * 4 + 0], b1 = s_w[t * 4 + 1], b2 = s_w[t * 4 + 2], b3 = s_w[t * 4 + 3];
        g_Wbit[(o * 9 + t) * 4 + 0] = b0;
        g_Wbit[(o * 9 + t) * 4 + 1] = b1;
        g_Wbit[(o * 9 + t) * 4 + 2] = b2;
        g_Wbit[(o * 9 + t) * 4 + 3] = b3;
        s_col[t] = 2 * (__popc(b0) + __popc(b1) + __popc(b2) + __popc(b3)) - 128;
    }
    __syncthreads();
    if (c < 16) {
        // one boundary type per thread
        float scale = redf[0] * (1.0f / 1152.0f);
        float inv = gamma[o] * rsqrtf(var[o] + 1e-5f);
        float sA = scale * inv;
        float sB = beta[o] - mean[o] * inv;
        if (c == 0) g_alpha[o] = -2.0f * sA;
        int type = c;
        int corr = 0;
#pragma unroll
        for (int t = 0; t < 9; t++) {
            int dy = t / 3 - 1, dx = t % 3 - 1;
            bool inval = ((type & 1) && dy < 0) || ((type & 2) && dy > 0) ||
                         ((type & 4) && dx < 0) || ((type & 8) && dx > 0);
            if (inval) corr += s_col[t];
        }
        g_bias[type * 128 + o] = (float)(1152 + corr) * sA + sB;
    }
}

// ---------------- K1: x (NCHW f32) -> padded bit-packed signs ----------------
__global__ void k_actbit(const float* __restrict__ x) {
    int hp = blockIdx.x;   // padded row 0..57
    int n = blockIdx.y;
    int tid = threadIdx.x; // 256
    uint32_t* ga = (uint32_t*)g_Abit;
    size_t rowbase = ((size_t)GUARD + (size_t)n * PIX + (size_t)hp * HP) * 4;
    if (hp == 0 || hp == HP - 1) {
        for (int i = tid; i < HP * 4; i += 256) ga[rowbase + i] = 0u;
        return;
    }
    __shared__ float s[128 * 57];
    const float* xp = x + (size_t)n * 128 * 3136 + (size_t)(hp - 1) * 56;
    for (int i = tid; i < 128 * 56; i += 256) {
        int c = i / 56;
        int wq = i - c * 56;
        s[c * 57 + wq] = xp[(size_t)c * 3136 + wq];
    }
    __syncthreads();
    int lane = tid & 31;
    int warp = tid >> 5;
    for (int j = warp; j < HP * 4; j += 8) {
        int wp = j >> 2;
        int g = j & 3;
        float v = (wp >= 1 && wp <= 56) ? s[(g * 32 + lane) * 57 + (wp - 1)] : -1.0f;
        unsigned m = __ballot_sync(0xFFFFFFFFu, v > 0.f);
        if (lane == 0) ga[rowbase + j] = m;
    }
}

// ---------------- K2: XNOR-popcount conv + BN + residual ----------------
__global__ void __launch_bounds__(128, 8)
k_pop(const float* __restrict__ x, float* __restrict__ out) {
    __shared__ uint32_t sW[128 * 9 * 4];   // 18 KB
    __shared__ float s_bias[16 * 128];     // 8 KB
    __shared__ float s_alpha[128];

    int tid = threadIdx.x;
    for (int i = tid; i < 128 * 9 * 4; i += 128) sW[i] = g_Wbit[i];
    for (int i = tid; i < 16 * 128; i += 128) s_bias[i] = g_bias[i];
    if (tid < 128) s_alpha[tid] = g_alpha[tid];
    __syncthreads();

    int p = blockIdx.x * 128 + tid;        // 0..200703 (1568*128 exact)
    int n = p / 3136;
    int rem = p - n * 3136;
    int h = rem / 56;
    int w = rem - h * 56;

    // load 9 tap words (registers), padded-grid addressing
    int arow = GUARD + n * PIX + (h + 1) * HP + (w + 1);
    uint4 A[9];
#pragma unroll
    for (int t = 0; t < 9; t++) {
        int dy = t / 3 - 1, dx = t % 3 - 1;
        A[t] = g_Abit[arow + dy * HP + dx];
    }
    int type = (h == 0 ? 1 : 0) | (h == 55 ? 2 : 0) | (w == 0 ? 4 : 0) | (w == 55 ? 8 : 0);
    const float* s_biasT = s_bias + type * 128;
    int base = n * 401408 + h * 56 + w;

    const uint4* Wv = (const uint4*)sW;
#pragma unroll 1
    for (int oc = 0; oc < 16; oc++) {
        float xv[8];
#pragma unroll
        for (int j = 0; j < 8; j++) xv[j] = x[base + (oc * 8 + j) * 3136];
#pragma unroll
        for (int j = 0; j < 8; j++) {
            int o = oc * 8 + j;
            int D = 0;
#pragma unroll
            for (int t = 0; t < 9; t++) {
                uint4 wv = Wv[o * 9 + t];
                D += __popc(A[t].x ^ wv.x) + __popc(A[t].y ^ wv.y) +
                     __popc(A[t].z ^ wv.z) + __popc(A[t].w ^ wv.w);
            }
            out[base + o * 3136] = fmaf((float)D, s_alpha[o], s_biasT[o]) + xv[j];
        }
    }
}

// ---------------- launch ----------------
extern "C" void kernel_launch(void* const* d_in, const int* in_sizes, int n_in,
                              void* d_out, int out_size) {
    (void)in_sizes; (void)n_in; (void)out_size;
    const float* x     = (const float*)d_in[0];
    const float* w     = (const float*)d_in[1];
    const float* gamma = (const float*)d_in[2];
    const float* beta  = (const float*)d_in[3];
    const float* mean  = (const float*)d_in[4];
    const float* var   = (const float*)d_in[5];
    float* out = (float*)d_out;

    k_actbit<<<dim3(HP, NB), 256>>>(x);
    k_wbit<<<128, 128>>>(w, gamma, beta, mean, var);
    k_pop<<<1568, 128>>>(x, out);
}

// round 6
// speedup vs baseline: 2.9117x; 1.3786x over previous
#include <cuda_runtime.h>
#include <cstdint>

// ---------------- problem constants ----------------
#define NB 64
#define HP 58
#define PIX (HP * HP)                  // 3364 padded pixels per image
#define ROWS_TOTAL (NB * PIX)          // 215296
#define GUARD 64
#define AROWS (ROWS_TOTAL + 2 * GUARD)

// ---------------- device scratch (no allocation allowed) ----------------
__device__ uint4    g_Abit[AROWS];         // bit-packed sign(x), padded NHWC (bit=1 <=> +1)
__device__ uint32_t g_Wbit2[128 * 4 * 12]; // sign(w) k-major: [o][k][t(9)+pad3]
__device__ float    g_alpha[128];          // -2 * scale_o * gamma_o * rsqrt(var+eps)
__device__ float    g_bias[16 * 128];      // (1152 + corr[type]) * sA + sB

// ---------------- K0: weights -> bits + folded scales + boundary bias table ----------------
__global__ void k_wbit(const float* __restrict__ w, const float* __restrict__ gamma,
                       const float* __restrict__ beta, const float* __restrict__ mean,
                       const float* __restrict__ var) {
    int o = blockIdx.x;
    int c = threadIdx.x;      // input channel 0..127
    int lane = c & 31;
    int g = c >> 5;           // channel group of 32 -> word index k
    __shared__ float redf[128];
    __shared__ uint32_t s_w[36];   // [t*4 + k]
    __shared__ int s_col[9];

    const float* wp = w + (o * 128 + c) * 9;
    float wv[9];
    float acc = 0.f;
#pragma unroll
    for (int t = 0; t < 9; t++) { wv[t] = wp[t]; acc += fabsf(wv[t]); }
    redf[c] = acc;

#pragma unroll
    for (int t = 0; t < 9; t++) {
        unsigned m = __ballot_sync(0xFFFFFFFFu, wv[t] > 0.f);
        if (lane == 0) s_w[t * 4 + g] = m;
    }
    __syncthreads();
#pragma unroll
    for (int s = 64; s > 0; s >>= 1) {
        if (c < s) redf[c] += redf[c + s];
        __syncthreads();
    }
    if (c < 36) {
        int t = c % 9;
        int k = c / 9;
        g_Wbit2[(o * 4 + k) * 12 + t] = s_w[t * 4 + k];
    }
    if (c < 9) {
        int t = c;
        uint32_t b0 = s_w[t * 4 + 0], b1 = s_w[t * 4 + 1], b2 = s_w[t * 4 + 2], b3 = s_w[t * 4 + 3];
        s_col[t] = 2 * (__popc(b0) + __popc(b1) + __popc(b2) + __popc(b3)) - 128;
    }
    __syncthreads();
    if (c < 16) {
        float scale = redf[0] * (1.0f / 1152.0f);
        float inv = gamma[o] * rsqrtf(var[o] + 1e-5f);
        float sA = scale * inv;
        float sB = beta[o] - mean[o] * inv;
        if (c == 0) g_alpha[o] = -2.0f * sA;
        int type = c;
        int corr = 0;
#pragma unroll
        for (int t = 0; t < 9; t++) {
            int dy = t / 3 - 1, dx = t % 3 - 1;
            bool inval = ((type & 1) && dy < 0) || ((type & 2) && dy > 0) ||
                         ((type & 4) && dx < 0) || ((type & 8) && dx > 0);
            if (inval) corr += s_col[t];
        }
        g_bias[type * 128 + o] = (float)(1152 + corr) * sA + sB;
    }
}

// ---------------- K1: x (NCHW f32) -> padded bit-packed signs ----------------
__global__ void k_actbit(const float* __restrict__ x) {
    int hp = blockIdx.x;   // padded row 0..57
    int n = blockIdx.y;
    int tid = threadIdx.x; // 256
    uint32_t* ga = (uint32_t*)g_Abit;
    size_t rowbase = ((size_t)GUARD + (size_t)n * PIX + (size_t)hp * HP) * 4;
    if (hp == 0 || hp == HP - 1) {
        for (int i = tid; i < HP * 4; i += 256) ga[rowbase + i] = 0u;
        return;
    }
    __shared__ float s[128 * 57];
    const float4* xp4 = (const float4*)(x + (size_t)n * 128 * 3136 + (size_t)(hp - 1) * 56);
    for (int i = tid; i < 128 * 14; i += 256) {
        int c = i / 14;
        int q = i - c * 14;
        float4 v = xp4[(size_t)c * 784 + q];
        float* sp = s + c * 57 + q * 4;
        sp[0] = v.x; sp[1] = v.y; sp[2] = v.z; sp[3] = v.w;
    }
    __syncthreads();
    int lane = tid & 31;
    int warp = tid >> 5;
    for (int j = warp; j < HP * 4; j += 8) {
        int wp = j >> 2;
        int g = j & 3;
        float v = (wp >= 1 && wp <= 56) ? s[(g * 32 + lane) * 57 + (wp - 1)] : -1.0f;
        unsigned m = __ballot_sync(0xFFFFFFFFu, v > 0.f);
        if (lane == 0) ga[rowbase + j] = m;
    }
}

// ---------------- CSA: 3 words -> (sum, carry), 2 LOP3 ----------------
__device__ __forceinline__ void csa(uint32_t a, uint32_t b, uint32_t c,
                                    uint32_t& s, uint32_t& cy) {
    s = a ^ b ^ c;
    cy = (a & b) | (a & c) | (b & c);
}

// ---------------- K2: XNOR-popcount conv (CSA-compressed) + BN + residual ----------------
__global__ void __launch_bounds__(128)
k_pop(const float* __restrict__ x, float* __restrict__ out) {
    __shared__ uint32_t sW[128 * 4 * 12];  // 24 KB, [o][k][12]
    __shared__ float s_bias[16 * 128];     // 8 KB
    __shared__ float s_alpha[128];

    int tid = threadIdx.x;
    for (int i = tid; i < 128 * 4 * 12; i += 128) sW[i] = g_Wbit2[i];
    for (int i = tid; i < 16 * 128; i += 128) s_bias[i] = g_bias[i];
    if (tid < 128) s_alpha[tid] = g_alpha[tid];
    __syncthreads();

    int p = blockIdx.x * 128 + tid;        // 1568*128 exact
    int n = p / 3136;
    int rem = p - n * 3136;
    int h = rem / 56;
    int w = rem - h * 56;

    // 9 tap words -> 36 u32 in registers (component-major access: Aw[t*4+k])
    int arow = GUARD + n * PIX + (h + 1) * HP + (w + 1);
    uint32_t Aw[36];
#pragma unroll
    for (int t = 0; t < 9; t++) {
        int dy = t / 3 - 1, dx = t % 3 - 1;
        uint4 v = g_Abit[arow + dy * HP + dx];
        Aw[t * 4 + 0] = v.x; Aw[t * 4 + 1] = v.y;
        Aw[t * 4 + 2] = v.z; Aw[t * 4 + 3] = v.w;
    }
    int type = (h == 0 ? 1 : 0) | (h == 55 ? 2 : 0) | (w == 0 ? 4 : 0) | (w == 55 ? 8 : 0);
    const float* s_biasT = s_bias + type * 128;
    int base = n * 401408 + h * 56 + w;

#pragma unroll 1
    for (int og = 0; og < 32; og++) {
        float xv[4];
#pragma unroll
        for (int j = 0; j < 4; j++) xv[j] = x[base + (og * 4 + j) * 3136];
#pragma unroll
        for (int j = 0; j < 4; j++) {
            int o = og * 4 + j;
            int acc1 = 0, acc2 = 0;
#pragma unroll
            for (int k = 0; k < 4; k++) {
                const uint32_t* wk = sW + (o * 4 + k) * 12;
                uint4 w03 = *(const uint4*)(wk);
                uint4 w47 = *(const uint4*)(wk + 4);
                uint32_t w8 = wk[8];
                uint32_t x0 = Aw[0 * 4 + k] ^ w03.x;
                uint32_t x1 = Aw[1 * 4 + k] ^ w03.y;
                uint32_t x2 = Aw[2 * 4 + k] ^ w03.z;
                uint32_t x3 = Aw[3 * 4 + k] ^ w03.w;
                uint32_t x4 = Aw[4 * 4 + k] ^ w47.x;
                uint32_t x5 = Aw[5 * 4 + k] ^ w47.y;
                uint32_t x6 = Aw[6 * 4 + k] ^ w47.z;
                uint32_t x7 = Aw[7 * 4 + k] ^ w47.w;
                uint32_t x8 = Aw[8 * 4 + k] ^ w8;
                uint32_t s0, c0, s1, c1, s2, c2, s3, c3;
                csa(x0, x1, x2, s0, c0);
                csa(x3, x4, x5, s1, c1);
                csa(x6, x7, x8, s2, c2);
                csa(s0, s1, s2, s3, c3);
                acc1 += __popc(s3);
                acc2 += __popc(c0) + __popc(c1) + __popc(c2) + __popc(c3);
            }
            int D = acc1 + 2 * acc2;
            out[base + o * 3136] = fmaf((float)D, s_alpha[o], s_biasT[o]) + xv[j];
        }
    }
}

// ---------------- launch ----------------
extern "C" void kernel_launch(void* const* d_in, const int* in_sizes, int n_in,
                              void* d_out, int out_size) {
    (void)in_sizes; (void)n_in; (void)out_size;
    const float* x     = (const float*)d_in[0];
    const float* w     = (const float*)d_in[1];
    const float* gamma = (const float*)d_in[2];
    const float* beta  = (const float*)d_in[3];
    const float* mean  = (const float*)d_in[4];
    const float* var   = (const float*)d_in[5];
    float* out = (float*)d_out;

    k_actbit<<<dim3(HP, NB), 256>>>(x);
    k_wbit<<<128, 128>>>(w, gamma, beta, mean, var);
    k_pop<<<1568, 128>>>(x, out);
}

// round 7
// speedup vs baseline: 2.9222x; 1.0036x over previous
#include <cuda_runtime.h>
#include <cstdint>

// ---------------- problem constants ----------------
#define NB 64
#define HP 58
#define PIX (HP * HP)                  // 3364 padded pixels per image
#define ROWS_TOTAL (NB * PIX)          // 215296
#define GUARD 64
#define AROWS (ROWS_TOTAL + 2 * GUARD)

// ---------------- device scratch (no allocation allowed) ----------------
__device__ uint4    g_Abit[AROWS];         // bit-packed sign(x), padded NHWC (bit=1 <=> +1)
__device__ uint32_t g_Wbit2[128 * 4 * 12]; // sign(w) k-major: [o][k][t(9)+pad3]
__device__ float    g_alpha[128];          // -2 * scale_o * gamma_o * rsqrt(var+eps)
__device__ float    g_bias[16 * 128];      // (1152 + corr[type]) * sA + sB

// ---------------- K0: weights -> bits + folded scales + boundary bias table ----------------
__global__ void k_wbit(const float* __restrict__ w, const float* __restrict__ gamma,
                       const float* __restrict__ beta, const float* __restrict__ mean,
                       const float* __restrict__ var) {
    int o = blockIdx.x;
    int c = threadIdx.x;      // input channel 0..127
    int lane = c & 31;
    int g = c >> 5;           // channel group of 32 -> word index k
    __shared__ float redf[128];
    __shared__ uint32_t s_w[36];   // [t*4 + k]
    __shared__ int s_col[9];

    const float* wp = w + (o * 128 + c) * 9;
    float wv[9];
    float acc = 0.f;
#pragma unroll
    for (int t = 0; t < 9; t++) { wv[t] = wp[t]; acc += fabsf(wv[t]); }
    redf[c] = acc;

#pragma unroll
    for (int t = 0; t < 9; t++) {
        unsigned m = __ballot_sync(0xFFFFFFFFu, wv[t] > 0.f);
        if (lane == 0) s_w[t * 4 + g] = m;
    }
    __syncthreads();
#pragma unroll
    for (int s = 64; s > 0; s >>= 1) {
        if (c < s) redf[c] += redf[c + s];
        __syncthreads();
    }
    if (c < 36) {
        int t = c % 9;
        int k = c / 9;
        g_Wbit2[(o * 4 + k) * 12 + t] = s_w[t * 4 + k];
    }
    if (c < 9) {
        int t = c;
        uint32_t b0 = s_w[t * 4 + 0], b1 = s_w[t * 4 + 1], b2 = s_w[t * 4 + 2], b3 = s_w[t * 4 + 3];
        s_col[t] = 2 * (__popc(b0) + __popc(b1) + __popc(b2) + __popc(b3)) - 128;
    }
    __syncthreads();
    if (c < 16) {
        float scale = redf[0] * (1.0f / 1152.0f);
        float inv = gamma[o] * rsqrtf(var[o] + 1e-5f);
        float sA = scale * inv;
        float sB = beta[o] - mean[o] * inv;
        if (c == 0) g_alpha[o] = -2.0f * sA;
        int type = c;
        int corr = 0;
#pragma unroll
        for (int t = 0; t < 9; t++) {
            int dy = t / 3 - 1, dx = t % 3 - 1;
            bool inval = ((type & 1) && dy < 0) || ((type & 2) && dy > 0) ||
                         ((type & 4) && dx < 0) || ((type & 8) && dx > 0);
            if (inval) corr += s_col[t];
        }
        g_bias[type * 128 + o] = (float)(1152 + corr) * sA + sB;
    }
}

// ---------------- K1a: zero the padded border words ----------------
__global__ void k_border() {
    int n = blockIdx.x;
    int tid = threadIdx.x;   // 256
    uint32_t* ga = (uint32_t*)g_Abit;
    size_t ibase = (size_t)GUARD * 4 + (size_t)n * PIX * 4;
    // rows hp=0 and hp=57: 2 * 58 pixels * 4 words = 464
    // cols wp=0 and wp=57 for hp=1..56: 2 * 56 * 4 = 448   (total 912)
    for (int i = tid; i < 912; i += 256) {
        size_t idx;
        if (i < 464) {
            int hp = (i < 232) ? 0 : 57;
            int r = (i < 232) ? i : (i - 232);
            idx = ibase + ((size_t)hp * HP) * 4 + r;      // r = wp*4+g
        } else {
            int j = i - 464;
            int wp = (j < 224) ? 0 : 57;
            int r = (j < 224) ? j : (j - 224);
            int hp = 1 + (r >> 2);
            idx = ibase + ((size_t)hp * HP + wp) * 4 + (r & 3);
        }
        ga[idx] = 0u;
    }
}

// ---------------- K1b: interior signs, streaming row-per-lane ----------------
__global__ void __launch_bounds__(128)
k_actbit(const float* __restrict__ x) {
    int h = blockIdx.x;    // 0..55
    int n = blockIdx.y;    // 0..63
    int lane = threadIdx.x & 31;
    int g = threadIdx.x >> 5;   // channel group 0..3
    uint32_t* ga = (uint32_t*)g_Abit;

    const float4* xp = (const float4*)(x + ((size_t)(n * 128 + g * 32 + lane)) * 3136 + (size_t)h * 56);
    size_t rowbase = ((size_t)GUARD + (size_t)n * PIX + (size_t)(h + 1) * HP) * 4;

#pragma unroll
    for (int q = 0; q < 14; q++) {
        float4 v = xp[q];
        unsigned m0 = __ballot_sync(0xFFFFFFFFu, v.x > 0.f);
        unsigned m1 = __ballot_sync(0xFFFFFFFFu, v.y > 0.f);
        unsigned m2 = __ballot_sync(0xFFFFFFFFu, v.z > 0.f);
        unsigned m3 = __ballot_sync(0xFFFFFFFFu, v.w > 0.f);
        if (lane < 4) {
            unsigned mj = (lane == 0) ? m0 : (lane == 1) ? m1 : (lane == 2) ? m2 : m3;
            ga[rowbase + (size_t)(q * 4 + lane + 1) * 4 + g] = mj;
        }
    }
}

// ---------------- CSA: 3 words -> (sum, carry), 2 LOP3 ----------------
__device__ __forceinline__ void csa(uint32_t a, uint32_t b, uint32_t c,
                                    uint32_t& s, uint32_t& cy) {
    s = a ^ b ^ c;
    cy = (a & b) | (a & c) | (b & c);
}

__device__ __forceinline__ void stcs(float* p, float v) {
    asm volatile("st.global.cs.f32 [%0], %1;" :: "l"(p), "f"(v) : "memory");
}

// ---------------- K2: XNOR-popcount conv (CSA-compressed) + BN + residual ----------------
__global__ void __launch_bounds__(128, 6)
k_pop(const float* __restrict__ x, float* __restrict__ out) {
    __shared__ uint32_t sW[128 * 4 * 12];  // 24 KB, [o][k][12]
    __shared__ float s_bias[16 * 128];     // 8 KB
    __shared__ float s_alpha[128];

    int tid = threadIdx.x;
    for (int i = tid; i < 128 * 4 * 12; i += 128) sW[i] = g_Wbit2[i];
    for (int i = tid; i < 16 * 128; i += 128) s_bias[i] = g_bias[i];
    if (tid < 128) s_alpha[tid] = g_alpha[tid];
    __syncthreads();

    int p = blockIdx.x * 128 + tid;        // 1568*128 exact
    int n = p / 3136;
    int rem = p - n * 3136;
    int h = rem / 56;
    int w = rem - h * 56;

    // 9 tap words -> 36 u32 in registers (component-major access: Aw[t*4+k])
    int arow = GUARD + n * PIX + (h + 1) * HP + (w + 1);
    uint32_t Aw[36];
#pragma unroll
    for (int t = 0; t < 9; t++) {
        int dy = t / 3 - 1, dx = t % 3 - 1;
        uint4 v = g_Abit[arow + dy * HP + dx];
        Aw[t * 4 + 0] = v.x; Aw[t * 4 + 1] = v.y;
        Aw[t * 4 + 2] = v.z; Aw[t * 4 + 3] = v.w;
    }
    int type = (h == 0 ? 1 : 0) | (h == 55 ? 2 : 0) | (w == 0 ? 4 : 0) | (w == 55 ? 8 : 0);
    const float* s_biasT = s_bias + type * 128;
    int base = n * 401408 + h * 56 + w;

#pragma unroll 1
    for (int og = 0; og < 32; og++) {
        float xv[4];
#pragma unroll
        for (int j = 0; j < 4; j++) xv[j] = x[base + (og * 4 + j) * 3136];
#pragma unroll
        for (int j = 0; j < 4; j++) {
            int o = og * 4 + j;
            int acc1 = 0, acc2 = 0;
#pragma unroll
            for (int k = 0; k < 4; k++) {
                const uint32_t* wk = sW + (o * 4 + k) * 12;
                uint4 w03 = *(const uint4*)(wk);
                uint4 w47 = *(const uint4*)(wk + 4);
                uint32_t w8 = wk[8];
                uint32_t x0 = Aw[0 * 4 + k] ^ w03.x;
                uint32_t x1 = Aw[1 * 4 + k] ^ w03.y;
                uint32_t x2 = Aw[2 * 4 + k] ^ w03.z;
                uint32_t x3 = Aw[3 * 4 + k] ^ w03.w;
                uint32_t x4 = Aw[4 * 4 + k] ^ w47.x;
                uint32_t x5 = Aw[5 * 4 + k] ^ w47.y;
                uint32_t x6 = Aw[6 * 4 + k] ^ w47.z;
                uint32_t x7 = Aw[7 * 4 + k] ^ w47.w;
                uint32_t x8 = Aw[8 * 4 + k] ^ w8;
                uint32_t s0, c0, s1, c1, s2, c2, s3, c3;
                csa(x0, x1, x2, s0, c0);
                csa(x3, x4, x5, s1, c1);
                csa(x6, x7, x8, s2, c2);
                csa(s0, s1, s2, s3, c3);
                acc1 += __popc(s3);
                acc2 += __popc(c0) + __popc(c1) + __popc(c2) + __popc(c3);
            }
            int D = acc1 + 2 * acc2;
            stcs(&out[base + o * 3136], fmaf((float)D, s_alpha[o], s_biasT[o]) + xv[j]);
        }
    }
}

// ---------------- launch ----------------
extern "C" void kernel_launch(void* const* d_in, const int* in_sizes, int n_in,
                              void* d_out, int out_size) {
    (void)in_sizes; (void)n_in; (void)out_size;
    const float* x     = (const float*)d_in[0];
    const float* w     = (const float*)d_in[1];
    const float* gamma = (const float*)d_in[2];
    const float* beta  = (const float*)d_in[3];
    const float* mean  = (const float*)d_in[4];
    const float* var   = (const float*)d_in[5];
    float* out = (float*)d_out;

    k_wbit<<<128, 128>>>(w, gamma, beta, mean, var);
    k_border<<<NB, 256>>>();
    k_actbit<<<dim3(56, NB), 128>>>(x);
    k_pop<<<1568, 128>>>(x, out);
}